// round 1
// baseline (speedup 1.0000x reference)
#include <cuda_runtime.h>

// Problem constants
#define CN  2048   // entities
#define CD  2048   // dim
#define CH  16     // heads
#define CHD 128    // per-head dim

// GEMM tiling
#define BM 128
#define BN 128
#define BK 16
#define TM 8
#define TN 8

// Scratch (device globals: allocation-free rule)
__device__ float g_Q[(size_t)CN * CD];
__device__ float g_K[(size_t)CN * CD];
__device__ float g_V[(size_t)CN * CD];
__device__ float g_O[(size_t)CN * CD];
__device__ float g_T[(size_t)CN * CD];
__device__ float g_S[(size_t)CH * CN * CN];   // 256 MB attention scores

// ---------------------------------------------------------------------------
// Tiled GEMM:  C = alpha * (A @ op(B)) [+ bias] [ReLU] [+ Res]
//   BT=true : C[m,n] = sum_k A[m,k] * B[n,k]   (x @ W^T, Q @ K^T)
//   BT=false: C[m,n] = sum_k A[m,k] * B[k,n]   (P @ V)
// Batched over blockIdx.z with element strides sA/sB/sC (0 for unbatched).
// No bounds checks: all dims are multiples of the tile sizes.
// ---------------------------------------------------------------------------
template <bool BT, bool RELU, bool RES>
__global__ void __launch_bounds__(256, 2) gemm_k(
    const float* __restrict__ A, int lda, long sA,
    const float* __restrict__ B, int ldb, long sB,
    float* __restrict__ C, int ldc, long sC,
    const float* __restrict__ bias,
    const float* __restrict__ Res, int ldr,
    int Kk, float alpha)
{
    __shared__ float As[BK][BM];
    __shared__ float Bs[BK][BN];

    const int z = blockIdx.z;
    A += (long)z * sA;
    B += (long)z * sB;
    C += (long)z * sC;

    const int tid  = threadIdx.x;
    const int brow = blockIdx.y * BM;
    const int bcol = blockIdx.x * BN;
    const int trow = (tid >> 4) * TM;   // 16x16 thread grid
    const int tcol = (tid & 15) * TN;

    float acc[TM][TN];
#pragma unroll
    for (int i = 0; i < TM; i++)
#pragma unroll
        for (int j = 0; j < TN; j++) acc[i][j] = 0.f;

    for (int k0 = 0; k0 < Kk; k0 += BK) {
        // ---- load A tile (BM x BK), transposed into As[k][m] ----
#pragma unroll
        for (int i = 0; i < 2; i++) {
            int l  = tid + i * 256;           // 512 float4 = 128x16 floats
            int r  = l >> 2;
            int c4 = (l & 3) << 2;
            float4 v = *(const float4*)(A + (size_t)(brow + r) * lda + k0 + c4);
            As[c4 + 0][r] = v.x;
            As[c4 + 1][r] = v.y;
            As[c4 + 2][r] = v.z;
            As[c4 + 3][r] = v.w;
        }
        // ---- load B tile into Bs[k][n] ----
        if (BT) {
#pragma unroll
            for (int i = 0; i < 2; i++) {
                int l  = tid + i * 256;
                int r  = l >> 2;
                int c4 = (l & 3) << 2;
                float4 v = *(const float4*)(B + (size_t)(bcol + r) * ldb + k0 + c4);
                Bs[c4 + 0][r] = v.x;
                Bs[c4 + 1][r] = v.y;
                Bs[c4 + 2][r] = v.z;
                Bs[c4 + 3][r] = v.w;
            }
        } else {
#pragma unroll
            for (int i = 0; i < 2; i++) {
                int l  = tid + i * 256;       // 16 rows x 128 cols
                int r  = l >> 5;
                int c4 = (l & 31) << 2;
                *(float4*)&Bs[r][c4] =
                    *(const float4*)(B + (size_t)(k0 + r) * ldb + bcol + c4);
            }
        }
        __syncthreads();

        // ---- compute ----
#pragma unroll
        for (int k = 0; k < BK; k++) {
            float4 a0 = *(const float4*)&As[k][trow];
            float4 a1 = *(const float4*)&As[k][trow + 4];
            float4 b0 = *(const float4*)&Bs[k][tcol];
            float4 b1 = *(const float4*)&Bs[k][tcol + 4];
            float ra[TM] = {a0.x, a0.y, a0.z, a0.w, a1.x, a1.y, a1.z, a1.w};
            float rb[TN] = {b0.x, b0.y, b0.z, b0.w, b1.x, b1.y, b1.z, b1.w};
#pragma unroll
            for (int i = 0; i < TM; i++)
#pragma unroll
                for (int j = 0; j < TN; j++)
                    acc[i][j] += ra[i] * rb[j];
        }
        __syncthreads();
    }

    // ---- fused epilogue ----
#pragma unroll
    for (int i = 0; i < TM; i++) {
        const int row = brow + trow + i;
#pragma unroll
        for (int j0 = 0; j0 < TN; j0 += 4) {
            float vv[4];
#pragma unroll
            for (int jj = 0; jj < 4; jj++) {
                const int col = bcol + tcol + j0 + jj;
                float x = acc[i][j0 + jj] * alpha;
                if (bias) x += bias[col];
                if (RELU) x = fmaxf(x, 0.f);
                if (RES)  x += Res[(size_t)row * ldr + col];
                vv[jj] = x;
            }
            float4 out = {vv[0], vv[1], vv[2], vv[3]};
            *(float4*)(C + (size_t)row * ldc + bcol + tcol + j0) = out;
        }
    }
}

// ---------------------------------------------------------------------------
// Row softmax over S: CH*CN rows of length CN. One CTA (256 thr) per row.
// ---------------------------------------------------------------------------
__global__ void __launch_bounds__(256) softmax_k(float* __restrict__ S)
{
    const size_t row = blockIdx.x;
    float* p = S + row * (size_t)CN;
    const int tid  = threadIdx.x;
    const int lane = tid & 31;
    const int w    = tid >> 5;

    float4 v0 = ((const float4*)p)[2 * tid];
    float4 v1 = ((const float4*)p)[2 * tid + 1];
    float e[8] = {v0.x, v0.y, v0.z, v0.w, v1.x, v1.y, v1.z, v1.w};

    // max
    float m = e[0];
#pragma unroll
    for (int i = 1; i < 8; i++) m = fmaxf(m, e[i]);
#pragma unroll
    for (int o = 16; o; o >>= 1) m = fmaxf(m, __shfl_xor_sync(0xffffffffu, m, o));
    __shared__ float redm[8];
    if (lane == 0) redm[w] = m;
    __syncthreads();
    float gm = redm[0];
#pragma unroll
    for (int i = 1; i < 8; i++) gm = fmaxf(gm, redm[i]);

    // exp + sum
    float s = 0.f;
#pragma unroll
    for (int i = 0; i < 8; i++) { e[i] = __expf(e[i] - gm); s += e[i]; }
#pragma unroll
    for (int o = 16; o; o >>= 1) s += __shfl_xor_sync(0xffffffffu, s, o);
    __shared__ float reds[8];
    if (lane == 0) reds[w] = s;
    __syncthreads();
    float gs = 0.f;
#pragma unroll
    for (int i = 0; i < 8; i++) gs += reds[i];

    const float inv = 1.f / gs;
    v0.x = e[0] * inv; v0.y = e[1] * inv; v0.z = e[2] * inv; v0.w = e[3] * inv;
    v1.x = e[4] * inv; v1.y = e[5] * inv; v1.z = e[6] * inv; v1.w = e[7] * inv;
    ((float4*)p)[2 * tid]     = v0;
    ((float4*)p)[2 * tid + 1] = v1;
}

// ---------------------------------------------------------------------------
// kernel_launch: 2 rounds of MHA + 2-layer ReLU MLP with residual.
// Entities live in d_out (copied in, updated in place).
// Inputs: entities, Wq, bq, Wk, bk, Wv, bv, W0, b0, W1, b1
// ---------------------------------------------------------------------------
extern "C" void kernel_launch(void* const* d_in, const int* in_sizes, int n_in,
                              void* d_out, int out_size)
{
    const float* ent = (const float*)d_in[0];
    const float* Wq  = (const float*)d_in[1];
    const float* bq  = (const float*)d_in[2];
    const float* Wk  = (const float*)d_in[3];
    const float* bk  = (const float*)d_in[4];
    const float* Wv  = (const float*)d_in[5];
    const float* bv  = (const float*)d_in[6];
    const float* W0  = (const float*)d_in[7];
    const float* b0  = (const float*)d_in[8];
    const float* W1  = (const float*)d_in[9];
    const float* b1  = (const float*)d_in[10];

    float* E = (float*)d_out;   // entities buffer (in/out)

    float *pQ, *pK, *pV, *pO, *pT, *pS;
    cudaGetSymbolAddress((void**)&pQ, g_Q);
    cudaGetSymbolAddress((void**)&pK, g_K);
    cudaGetSymbolAddress((void**)&pV, g_V);
    cudaGetSymbolAddress((void**)&pO, g_O);
    cudaGetSymbolAddress((void**)&pT, g_T);
    cudaGetSymbolAddress((void**)&pS, g_S);

    cudaMemcpyAsync(E, ent, (size_t)CN * CD * sizeof(float),
                    cudaMemcpyDeviceToDevice);

    const float scale = 0.08838834764831845f;  // 1/sqrt(128)
    dim3 thr(256);
    dim3 gFull(CD / BN, CN / BM, 1);      // (16,16,1)
    dim3 gScore(CN / BN, CN / BM, CH);    // (16,16,16)
    dim3 gAV(CHD / BN, CN / BM, CH);      // (1,16,16)

    for (int r = 0; r < 2; r++) {
        // Q/K/V projections: E @ W^T + b
        gemm_k<true, false, false><<<gFull, thr>>>(
            E, CD, 0,  Wq, CD, 0,  pQ, CD, 0,  bq, nullptr, 0, CD, 1.f);
        gemm_k<true, false, false><<<gFull, thr>>>(
            E, CD, 0,  Wk, CD, 0,  pK, CD, 0,  bk, nullptr, 0, CD, 1.f);
        gemm_k<true, false, false><<<gFull, thr>>>(
            E, CD, 0,  Wv, CD, 0,  pV, CD, 0,  bv, nullptr, 0, CD, 1.f);

        // S[h] = scale * Qh @ Kh^T   (batched over heads)
        gemm_k<true, false, false><<<gScore, thr>>>(
            pQ, CD, (long)CHD,  pK, CD, (long)CHD,
            pS, CN, (long)CN * CN,  nullptr, nullptr, 0, CHD, scale);

        // softmax rows
        softmax_k<<<CH * CN, 256>>>(pS);

        // O[h] = P[h] @ Vh   (batched over heads; output strided into [N,D])
        gemm_k<false, false, false><<<gAV, thr>>>(
            pS, CN, (long)CN * CN,  pV, CD, (long)CHD,
            pO, CD, (long)CHD,  nullptr, nullptr, 0, CN, 1.f);

        // MLP: T = relu(O @ W0^T + b0);  E = E + relu(T @ W1^T + b1)
        gemm_k<true, true, false><<<gFull, thr>>>(
            pO, CD, 0,  W0, CD, 0,  pT, CD, 0,  b0, nullptr, 0, CD, 1.f);
        gemm_k<true, true, true><<<gFull, thr>>>(
            pT, CD, 0,  W1, CD, 0,  E, CD, 0,  b1, E, CD, CD, 1.f);
    }
}

// round 8
// speedup vs baseline: 2.2092x; 2.2092x over previous
#include <cuda_runtime.h>
#include <cuda_bf16.h>
#include <cstdint>

#define CN 2048
#define CD 2048
#define CH 16
#define CHD 128
typedef __nv_bfloat16 bf16;

// GEMM geometry: 128x128 CTA tile, BK=32 (bf16), mma.sync.m16n8k16 path
#define RSTRIDE 80                 // 64B data + 16B pad per row (ldmatrix conflict-free)
#define BUFB (128 * RSTRIDE)       // 10240 B per operand buffer
#define STAGEB (4 * BUFB)          // Ahi, Alo, Bhi, Blo
#define NST 3
#define DSM (NST * STAGEB)         // 122880 B

// ---------------- device scratch (allocation-free rule) ----------------
__device__ float g_S [(size_t)CH * CN * CN];      // scores fp32
__device__ float g_Vf[(size_t)CN * CD];           // V fp32 (pre-transpose)
__device__ bf16 g_Wh[5][(size_t)CD * CD];
__device__ bf16 g_Wl[5][(size_t)CD * CD];
__device__ bf16 g_Eh [(size_t)CN * CD], g_El [(size_t)CN * CD];
__device__ bf16 g_Qh [(size_t)CN * CD], g_Ql [(size_t)CN * CD];
__device__ bf16 g_Kh [(size_t)CN * CD], g_Kl [(size_t)CN * CD];
__device__ bf16 g_Vth[(size_t)CD * CN], g_Vtl[(size_t)CD * CN];  // V^T per head
__device__ bf16 g_Ph [(size_t)CH * CN * CN], g_Pl[(size_t)CH * CN * CN];
__device__ bf16 g_Oh [(size_t)CN * CD], g_Ol [(size_t)CN * CD];
__device__ bf16 g_Th [(size_t)CN * CD], g_Tl [(size_t)CN * CD];

// ---------------- helpers ----------------
__device__ __forceinline__ uint32_t smem_u32(const void* p) {
    uint32_t a;
    asm("{ .reg .u64 t; cvta.to.shared.u64 t, %1; cvt.u32.u64 %0, t; }" : "=r"(a) : "l"(p));
    return a;
}
__device__ __forceinline__ void cp16(uint32_t dst, const void* src) {
    uint64_t g = __cvta_generic_to_global(src);
    asm volatile("cp.async.cg.shared.global [%0], [%1], 16;" :: "r"(dst), "l"(g) : "memory");
}
__device__ __forceinline__ void cp_commit() { asm volatile("cp.async.commit_group;" ::: "memory"); }
template <int N> __device__ __forceinline__ void cp_wait() {
    asm volatile("cp.async.wait_group %0;" :: "n"(N) : "memory");
}
__device__ __forceinline__ void ldsm4(uint32_t* d, uint32_t addr) {
    asm volatile("ldmatrix.sync.aligned.m8n8.x4.shared.b16 {%0,%1,%2,%3}, [%4];"
                 : "=r"(d[0]), "=r"(d[1]), "=r"(d[2]), "=r"(d[3]) : "r"(addr));
}
__device__ __forceinline__ void mma16816(float* c, const uint32_t* a, const uint32_t* b) {
    asm volatile("mma.sync.aligned.m16n8k16.row.col.f32.bf16.bf16.f32 "
                 "{%0,%1,%2,%3}, {%4,%5,%6,%7}, {%8,%9}, {%0,%1,%2,%3};"
                 : "+f"(c[0]), "+f"(c[1]), "+f"(c[2]), "+f"(c[3])
                 : "r"(a[0]), "r"(a[1]), "r"(a[2]), "r"(a[3]), "r"(b[0]), "r"(b[1]));
}
__device__ __forceinline__ uint32_t packbf(bf16 a, bf16 b) {
    __nv_bfloat162 t; t.x = a; t.y = b;
    return *reinterpret_cast<uint32_t*>(&t);
}

// ---------------------------------------------------------------------------
// bf16x3 GEMM (mma.sync): C = alpha * (A @ B^T) [+bias][ReLU][+Res]
// A: [M,K] hi/lo K-major, B: [N,K] hi/lo K-major. 128x128 tile per CTA.
// Outputs: WF32 -> fp32 C, WPAIR -> hi/lo bf16 pair. Batched over blockIdx.z.
// ---------------------------------------------------------------------------
template <bool RELU, bool RES, bool WF32, bool WPAIR>
__global__ void __launch_bounds__(256, 1) mma_gemm(
    const bf16* __restrict__ Ah, const bf16* __restrict__ Al, int lda, long sA,
    const bf16* __restrict__ Bh, const bf16* __restrict__ Bl, int ldb, long sB,
    float* __restrict__ C, int ldc, long sC,
    bf16* __restrict__ Ch, bf16* __restrict__ Cl, int ldcp, long sCp,
    const float* __restrict__ bias,
    const float* __restrict__ Res, int ldr,
    int K, float alpha)
{
    extern __shared__ __align__(16) char dsm_raw[];
    const uint32_t smbase = smem_u32(dsm_raw);

    const int tid  = threadIdx.x;
    const int lane = tid & 31;
    const int w    = tid >> 5;
    const int wm   = w >> 2;        // 0..1  -> 64-row slab
    const int wn   = w & 3;         // 0..3  -> 32-col slab

    const long z = blockIdx.z;
    Ah += z * sA; Al += z * sA;
    Bh += z * sB; Bl += z * sB;
    const long am0 = (long)blockIdx.y * 128;
    const long bn0 = (long)blockIdx.x * 128;

    const int nch = K / 32;

    // ---- per-lane ldmatrix offsets (bytes, within a buffer) ----
    const int i8 = lane & 7, sel = lane >> 3;
    uint32_t aoff[4], boff[2];
#pragma unroll
    for (int mt = 0; mt < 4; mt++)
        aoff[mt] = (uint32_t)((wm * 64 + mt * 16 + i8 + (sel & 1) * 8) * RSTRIDE
                              + (sel >> 1) * 16);
#pragma unroll
    for (int np = 0; np < 2; np++)
        boff[np] = (uint32_t)((wn * 32 + np * 16 + i8 + ((sel >> 1) & 1) * 8) * RSTRIDE
                              + (sel & 1) * 16);

    // ---- stage loader: 4 buffers x 128 rows x 64B via cp.async ----
    auto load_stage = [&](int s, int kchunk) {
        const int k0 = kchunk * 32;       // element offset
        const uint32_t sb = smbase + s * STAGEB;
#pragma unroll
        for (int it = 0; it < 8; it++) {
            int e  = tid + (it << 8);     // 0..2047
            int buf = e >> 9;             // 512 chunks per buffer
            int ee  = e & 511;
            int r   = ee >> 2;
            int cc  = ee & 3;
            const bf16* src;
            if (buf == 0)      src = Ah + (am0 + r) * (long)lda + k0 + cc * 8;
            else if (buf == 1) src = Al + (am0 + r) * (long)lda + k0 + cc * 8;
            else if (buf == 2) src = Bh + (bn0 + r) * (long)ldb + k0 + cc * 8;
            else               src = Bl + (bn0 + r) * (long)ldb + k0 + cc * 8;
            cp16(sb + buf * BUFB + (uint32_t)(r * RSTRIDE + cc * 16), src);
        }
        cp_commit();
    };

    int li = 0;
    while (li < NST && li < nch) { load_stage(li % NST, li); li++; }

    float acc[4][4][4];
#pragma unroll
    for (int a = 0; a < 4; a++)
#pragma unroll
        for (int b = 0; b < 4; b++)
#pragma unroll
            for (int c = 0; c < 4; c++) acc[a][b][c] = 0.f;

    for (int c = 0; c < nch; c++) {
        const int nleft = li - c - 1;
        if (nleft >= 2) cp_wait<2>();
        else if (nleft == 1) cp_wait<1>();
        else cp_wait<0>();
        __syncthreads();

        const uint32_t sb  = smbase + (c % NST) * STAGEB;
        const uint32_t bah = sb, bal = sb + BUFB, bbh = sb + 2 * BUFB, bbl = sb + 3 * BUFB;

#pragma unroll
        for (int ks = 0; ks < 64; ks += 32) {   // two k16 halves (byte offset)
            uint32_t AH[4][4], AL[4][4], BH[4][2], BL[4][2];
#pragma unroll
            for (int mt = 0; mt < 4; mt++) {
                ldsm4(AH[mt], bah + aoff[mt] + ks);
                ldsm4(AL[mt], bal + aoff[mt] + ks);
            }
#pragma unroll
            for (int np = 0; np < 2; np++) {
                uint32_t th[4], tl[4];
                ldsm4(th, bbh + boff[np] + ks);
                ldsm4(tl, bbl + boff[np] + ks);
                BH[2 * np][0] = th[0]; BH[2 * np][1] = th[1];
                BH[2 * np + 1][0] = th[2]; BH[2 * np + 1][1] = th[3];
                BL[2 * np][0] = tl[0]; BL[2 * np][1] = tl[1];
                BL[2 * np + 1][0] = tl[2]; BL[2 * np + 1][1] = tl[3];
            }
#pragma unroll
            for (int mt = 0; mt < 4; mt++)
#pragma unroll
                for (int nt = 0; nt < 4; nt++) {
                    mma16816(acc[mt][nt], AH[mt], BH[nt]);
                    mma16816(acc[mt][nt], AH[mt], BL[nt]);
                    mma16816(acc[mt][nt], AL[mt], BH[nt]);
                }
        }
        __syncthreads();

        if (li < nch) { load_stage(li % NST, li); li++; }
    }

    // ---- epilogue ----
    const int g  = lane >> 2;
    const int t2 = (lane & 3) * 2;
    const bool hasb = (bias != nullptr);

#pragma unroll
    for (int mt = 0; mt < 4; mt++) {
        const long r = am0 + wm * 64 + mt * 16 + g;
#pragma unroll
        for (int nt = 0; nt < 4; nt++) {
            const long cc = bn0 + wn * 32 + nt * 8 + t2;
            float b0v = 0.f, b1v = 0.f;
            if (hasb) { b0v = bias[cc]; b1v = bias[cc + 1]; }
#pragma unroll
            for (int h = 0; h < 2; h++) {
                const long rr = r + h * 8;
                float v0 = acc[mt][nt][2 * h]     * alpha + b0v;
                float v1 = acc[mt][nt][2 * h + 1] * alpha + b1v;
                if (RELU) { v0 = fmaxf(v0, 0.f); v1 = fmaxf(v1, 0.f); }
                if (RES)  { v0 += Res[rr * (long)ldr + cc];
                            v1 += Res[rr * (long)ldr + cc + 1]; }
                if (WF32) {
                    float2 o = {v0, v1};
                    *(float2*)(C + z * sC + rr * (long)ldc + cc) = o;
                }
                if (WPAIR) {
                    bf16 h0 = __float2bfloat16(v0);
                    bf16 l0 = __float2bfloat16(v0 - __bfloat162float(h0));
                    bf16 h1 = __float2bfloat16(v1);
                    bf16 l1 = __float2bfloat16(v1 - __bfloat162float(h1));
                    *(uint32_t*)(Ch + z * sCp + rr * (long)ldcp + cc) = packbf(h0, h1);
                    *(uint32_t*)(Cl + z * sCp + rr * (long)ldcp + cc) = packbf(l0, l1);
                }
            }
        }
    }
}

// ---------------------------------------------------------------------------
// fp32 -> hi/lo bf16 split (elementwise, vectorized)
// ---------------------------------------------------------------------------
__global__ void __launch_bounds__(256) f2pair_k(const float* __restrict__ in,
                                               bf16* __restrict__ h,
                                               bf16* __restrict__ l, int n4)
{
    int i = blockIdx.x * 256 + threadIdx.x;
    if (i >= n4) return;
    float4 v = ((const float4*)in)[i];
    bf16 h0 = __float2bfloat16(v.x), h1 = __float2bfloat16(v.y);
    bf16 h2 = __float2bfloat16(v.z), h3 = __float2bfloat16(v.w);
    bf16 l0 = __float2bfloat16(v.x - __bfloat162float(h0));
    bf16 l1 = __float2bfloat16(v.y - __bfloat162float(h1));
    bf16 l2 = __float2bfloat16(v.z - __bfloat162float(h2));
    bf16 l3 = __float2bfloat16(v.w - __bfloat162float(h3));
    uint2 hv = {packbf(h0, h1), packbf(h2, h3)};
    uint2 lv = {packbf(l0, l1), packbf(l2, l3)};
    ((uint2*)h)[i] = hv;
    ((uint2*)l)[i] = lv;
}

// ---------------------------------------------------------------------------
// V transpose + split: Vt[d_global][n] = V[n][d_global] as hi/lo bf16
// ---------------------------------------------------------------------------
__global__ void __launch_bounds__(256) vtrans_k(const float* __restrict__ V,
                                                bf16* __restrict__ Vth,
                                                bf16* __restrict__ Vtl)
{
    __shared__ float t[32][33];
    const int tx = threadIdx.x, ty = threadIdx.y;
    const int d0 = blockIdx.x * 32, n0 = blockIdx.y * 32;
#pragma unroll
    for (int i = 0; i < 4; i++)
        t[ty + i * 8][tx] = V[(long)(n0 + ty + i * 8) * CD + d0 + tx];
    __syncthreads();
#pragma unroll
    for (int i = 0; i < 4; i++) {
        float v = t[tx][ty + i * 8];
        bf16 h = __float2bfloat16(v);
        bf16 l = __float2bfloat16(v - __bfloat162float(h));
        long o = (long)(d0 + ty + i * 8) * CN + n0 + tx;
        Vth[o] = h;
        Vtl[o] = l;
    }
}

// ---------------------------------------------------------------------------
// Row softmax fused with hi/lo bf16 conversion of P
// ---------------------------------------------------------------------------
__global__ void __launch_bounds__(256) softmax_conv_k(const float* __restrict__ S,
                                                      bf16* __restrict__ Ph,
                                                      bf16* __restrict__ Pl)
{
    const size_t row = blockIdx.x;
    const float* p = S + row * (size_t)CN;
    const int tid = threadIdx.x, lane = tid & 31, w = tid >> 5;

    float4 v0 = ((const float4*)p)[2 * tid];
    float4 v1 = ((const float4*)p)[2 * tid + 1];
    float e[8] = {v0.x, v0.y, v0.z, v0.w, v1.x, v1.y, v1.z, v1.w};

    float m = e[0];
#pragma unroll
    for (int i = 1; i < 8; i++) m = fmaxf(m, e[i]);
#pragma unroll
    for (int o = 16; o; o >>= 1) m = fmaxf(m, __shfl_xor_sync(0xffffffffu, m, o));
    __shared__ float redm[8], reds[8];
    if (lane == 0) redm[w] = m;
    __syncthreads();
    float gm = redm[0];
#pragma unroll
    for (int i = 1; i < 8; i++) gm = fmaxf(gm, redm[i]);

    float s = 0.f;
#pragma unroll
    for (int i = 0; i < 8; i++) { e[i] = __expf(e[i] - gm); s += e[i]; }
#pragma unroll
    for (int o = 16; o; o >>= 1) s += __shfl_xor_sync(0xffffffffu, s, o);
    if (lane == 0) reds[w] = s;
    __syncthreads();
    float gs = 0.f;
#pragma unroll
    for (int i = 0; i < 8; i++) gs += reds[i];
    const float inv = 1.f / gs;

    uint32_t hw[4], lw[4];
#pragma unroll
    for (int j = 0; j < 4; j++) {
        float a = e[2 * j] * inv, b = e[2 * j + 1] * inv;
        bf16 ha = __float2bfloat16(a), hb = __float2bfloat16(b);
        bf16 la = __float2bfloat16(a - __bfloat162float(ha));
        bf16 lb = __float2bfloat16(b - __bfloat162float(hb));
        hw[j] = packbf(ha, hb);
        lw[j] = packbf(la, lb);
    }
    uint4 hv = {hw[0], hw[1], hw[2], hw[3]};
    uint4 lv = {lw[0], lw[1], lw[2], lw[3]};
    ((uint4*)(Ph + row * (size_t)CN))[tid] = hv;
    ((uint4*)(Pl + row * (size_t)CN))[tid] = lv;
}

// ---------------------------------------------------------------------------
extern "C" void kernel_launch(void* const* d_in, const int* in_sizes, int n_in,
                              void* d_out, int out_size)
{
    const float* ent = (const float*)d_in[0];
    const float* W[5]  = {(const float*)d_in[1], (const float*)d_in[3],
                          (const float*)d_in[5], (const float*)d_in[7],
                          (const float*)d_in[9]};                       // Wq Wk Wv W0 W1
    const float* bq = (const float*)d_in[2];
    const float* bk = (const float*)d_in[4];
    const float* bv = (const float*)d_in[6];
    const float* b0 = (const float*)d_in[8];
    const float* b1 = (const float*)d_in[10];

    float* E = (float*)d_out;

    float *pS, *pVf;
    bf16 *pWh, *pWl, *pEh, *pEl, *pQh, *pQl, *pKh, *pKl, *pVth, *pVtl;
    bf16 *pPh, *pPl, *pOh, *pOl, *pTh, *pTl;
    cudaGetSymbolAddress((void**)&pS,  g_S);
    cudaGetSymbolAddress((void**)&pVf, g_Vf);
    cudaGetSymbolAddress((void**)&pWh, g_Wh);
    cudaGetSymbolAddress((void**)&pWl, g_Wl);
    cudaGetSymbolAddress((void**)&pEh, g_Eh);   cudaGetSymbolAddress((void**)&pEl, g_El);
    cudaGetSymbolAddress((void**)&pQh, g_Qh);   cudaGetSymbolAddress((void**)&pQl, g_Ql);
    cudaGetSymbolAddress((void**)&pKh, g_Kh);   cudaGetSymbolAddress((void**)&pKl, g_Kl);
    cudaGetSymbolAddress((void**)&pVth, g_Vth); cudaGetSymbolAddress((void**)&pVtl, g_Vtl);
    cudaGetSymbolAddress((void**)&pPh, g_Ph);   cudaGetSymbolAddress((void**)&pPl, g_Pl);
    cudaGetSymbolAddress((void**)&pOh, g_Oh);   cudaGetSymbolAddress((void**)&pOl, g_Ol);
    cudaGetSymbolAddress((void**)&pTh, g_Th);   cudaGetSymbolAddress((void**)&pTl, g_Tl);

    cudaFuncSetAttribute(mma_gemm<false, false, false, true>,
                         cudaFuncAttributeMaxDynamicSharedMemorySize, DSM);
    cudaFuncSetAttribute(mma_gemm<false, false, true, false>,
                         cudaFuncAttributeMaxDynamicSharedMemorySize, DSM);
    cudaFuncSetAttribute(mma_gemm<true, false, false, true>,
                         cudaFuncAttributeMaxDynamicSharedMemorySize, DSM);
    cudaFuncSetAttribute(mma_gemm<true, true, true, true>,
                         cudaFuncAttributeMaxDynamicSharedMemorySize, DSM);

    const size_t WSZ = (size_t)CD * CD;
    const int n4 = (int)(WSZ / 4);
    const float scale = 0.08838834764831845f;   // 1/sqrt(128)

    cudaMemcpyAsync(E, ent, (size_t)CN * CD * sizeof(float), cudaMemcpyDeviceToDevice);
    f2pair_k<<<n4 / 256, 256>>>(ent, pEh, pEl, n4);
    for (int i = 0; i < 5; i++)
        f2pair_k<<<n4 / 256, 256>>>(W[i], pWh + i * WSZ, pWl + i * WSZ, n4);

    dim3 thr(256);
    dim3 gFull(16, 16, 1);
    dim3 gScore(16, 16, CH);
    dim3 gPV(1, 16, CH);

    for (int r = 0; r < 2; r++) {
        // Q = E @ Wq^T + bq -> hi/lo pair
        mma_gemm<false, false, false, true><<<gFull, thr, DSM>>>(
            pEh, pEl, CD, 0, pWh + 0 * WSZ, pWl + 0 * WSZ, CD, 0,
            nullptr, 0, 0, pQh, pQl, CD, 0, bq, nullptr, 0, CD, 1.f);
        // K
        mma_gemm<false, false, false, true><<<gFull, thr, DSM>>>(
            pEh, pEl, CD, 0, pWh + 1 * WSZ, pWl + 1 * WSZ, CD, 0,
            nullptr, 0, 0, pKh, pKl, CD, 0, bk, nullptr, 0, CD, 1.f);
        // V -> fp32
        mma_gemm<false, false, true, false><<<gFull, thr, DSM>>>(
            pEh, pEl, CD, 0, pWh + 2 * WSZ, pWl + 2 * WSZ, CD, 0,
            pVf, CD, 0, nullptr, nullptr, 0, 0, bv, nullptr, 0, CD, 1.f);
        // V^T + split
        vtrans_k<<<dim3(CD / 32, CN / 32), dim3(32, 8)>>>(pVf, pVth, pVtl);

        // S[h] = scale * Qh @ Kh^T
        mma_gemm<false, false, true, false><<<gScore, thr, DSM>>>(
            pQh, pQl, CD, (long)CHD, pKh, pKl, CD, (long)CHD,
            pS, CN, (long)CN * CN, nullptr, nullptr, 0, 0,
            nullptr, nullptr, 0, CHD, scale);

        // softmax + split P
        softmax_conv_k<<<CH * CN, 256>>>(pS, pPh, pPl);

        // O[h] = P[h] @ V[h]  (B = V^T per head, K-major)
        mma_gemm<false, false, false, true><<<gPV, thr, DSM>>>(
            pPh, pPl, CN, (long)CN * CN, pVth, pVtl, CN, (long)CHD * CN,
            nullptr, 0, 0, pOh, pOl, CD, (long)CHD,
            nullptr, nullptr, 0, CN, 1.f);

        // T = relu(O @ W0^T + b0) -> pair
        mma_gemm<true, false, false, true><<<gFull, thr, DSM>>>(
            pOh, pOl, CD, 0, pWh + 3 * WSZ, pWl + 3 * WSZ, CD, 0,
            nullptr, 0, 0, pTh, pTl, CD, 0, b0, nullptr, 0, CD, 1.f);

        // E = E + relu(T @ W1^T + b1) -> fp32 E and pair for next round
        mma_gemm<true, true, true, true><<<gFull, thr, DSM>>>(
            pTh, pTl, CD, 0, pWh + 4 * WSZ, pWl + 4 * WSZ, CD, 0,
            E, CD, 0, pEh, pEl, CD, 0, b1, E, CD, CD, 1.f);
    }
}